// round 1
// baseline (speedup 1.0000x reference)
#include <cuda_runtime.h>

// Problem constants
#define BB   8
#define CC   512
#define HH   64
#define WWW  64
#define NPIX 4096         // H*W
#define OC   1536         // 3*C
#define ND   4            // num dilations (1,2,4,8)
#define BD   128          // channels per branch
#define HD   64           // head dim (2 heads per branch)

// Scratch (static device allocations — allowed)
__device__ float g_qkv[(size_t)BB * OC * NPIX];   // 192 MB
__device__ float g_pooled[BB * CC];
__device__ float g_gate[BB * ND];

// ---------------------------------------------------------------------------
// QKV projection GEMM: qkv[b,o,n] = sum_c w[o,c] * x[b,c,n]
// M=1536 (o), N=4096 (n), K=512 (c), batched over b.
// 128x128 block tile, BK=16, 256 threads, 8x8 register tile per thread.
// ---------------------------------------------------------------------------
#define BM 128
#define BN 128
#define BK 16
#define TM 8
#define TN 8

__global__ __launch_bounds__(256) void gemm_qkv_kernel(
    const float* __restrict__ x, const float* __restrict__ w)
{
    __shared__ float As[BK][BM];   // w tile, transposed: [k][m]
    __shared__ float Bs[BK][BN];   // x tile: [k][n]

    const int b     = blockIdx.z;
    const int mBase = blockIdx.y * BM;
    const int nBase = blockIdx.x * BN;
    const int tid   = threadIdx.x;

    // A-load mapping: 128 rows (m) x 16 cols (k). Each thread: 8 consecutive k.
    const int aRow = tid & 127;          // 0..127
    const int aCol = (tid >> 7) * 8;     // 0 or 8
    // B-load mapping: 16 rows (k) x 128 cols (n). Each thread: 8 consecutive n.
    const int bRow = tid >> 4;           // 0..15
    const int bCol = (tid & 15) * 8;     // 0..120

    const int tm = (tid >> 4) * TM;      // 0..120
    const int tn = (tid & 15) * TN;      // 0..120

    float acc[TM][TN];
    #pragma unroll
    for (int i = 0; i < TM; i++)
        #pragma unroll
        for (int j = 0; j < TN; j++) acc[i][j] = 0.f;

    const float* wRow = w + (size_t)(mBase + aRow) * CC + aCol;
    const float* xRow = x + ((size_t)b * CC + bRow) * NPIX + nBase + bCol;

    for (int kt = 0; kt < CC; kt += BK) {
        // Load A (w) tile
        float4 a0 = *reinterpret_cast<const float4*>(wRow + kt + 0);
        float4 a1 = *reinterpret_cast<const float4*>(wRow + kt + 4);
        As[aCol + 0][aRow] = a0.x;  As[aCol + 1][aRow] = a0.y;
        As[aCol + 2][aRow] = a0.z;  As[aCol + 3][aRow] = a0.w;
        As[aCol + 4][aRow] = a1.x;  As[aCol + 5][aRow] = a1.y;
        As[aCol + 6][aRow] = a1.z;  As[aCol + 7][aRow] = a1.w;
        // Load B (x) tile
        float4 b0 = *reinterpret_cast<const float4*>(xRow + (size_t)kt * NPIX + 0);
        float4 b1 = *reinterpret_cast<const float4*>(xRow + (size_t)kt * NPIX + 4);
        *reinterpret_cast<float4*>(&Bs[bRow][bCol + 0]) = b0;
        *reinterpret_cast<float4*>(&Bs[bRow][bCol + 4]) = b1;

        __syncthreads();

        #pragma unroll
        for (int k = 0; k < BK; k++) {
            float aReg[TM], bReg[TN];
            #pragma unroll
            for (int i = 0; i < TM; i++) aReg[i] = As[k][tm + i];
            #pragma unroll
            for (int j = 0; j < TN; j++) bReg[j] = Bs[k][tn + j];
            #pragma unroll
            for (int i = 0; i < TM; i++)
                #pragma unroll
                for (int j = 0; j < TN; j++)
                    acc[i][j] = fmaf(aReg[i], bReg[j], acc[i][j]);
        }
        __syncthreads();
    }

    // Epilogue
    #pragma unroll
    for (int i = 0; i < TM; i++) {
        float* outp = g_qkv + ((size_t)b * OC + mBase + tm + i) * NPIX + nBase + tn;
        float4 v0 = make_float4(acc[i][0], acc[i][1], acc[i][2], acc[i][3]);
        float4 v1 = make_float4(acc[i][4], acc[i][5], acc[i][6], acc[i][7]);
        *reinterpret_cast<float4*>(outp + 0) = v0;
        *reinterpret_cast<float4*>(outp + 4) = v1;
    }
}

// ---------------------------------------------------------------------------
// Spatial mean pool: g_pooled[b,c] = mean_n x[b,c,n]
// One block per (c, b), 256 threads.
// ---------------------------------------------------------------------------
__global__ __launch_bounds__(256) void pool_kernel(const float* __restrict__ x)
{
    const int c = blockIdx.x;
    const int b = blockIdx.y;
    const float* p = x + ((size_t)b * CC + c) * NPIX;

    float s = 0.f;
    for (int i = threadIdx.x; i < NPIX; i += 256) s += p[i];

    // warp + smem reduce
    #pragma unroll
    for (int off = 16; off > 0; off >>= 1)
        s += __shfl_xor_sync(0xFFFFFFFFu, s, off);
    __shared__ float sred[8];
    if ((threadIdx.x & 31) == 0) sred[threadIdx.x >> 5] = s;
    __syncthreads();
    if (threadIdx.x == 0) {
        float tot = 0.f;
        #pragma unroll
        for (int i = 0; i < 8; i++) tot += sred[i];
        g_pooled[b * CC + c] = tot * (1.0f / NPIX);
    }
}

// ---------------------------------------------------------------------------
// Gate: g_gate[b,i] = softmax_i( pooled[b] . w_gate[i] + b_gate[i] )
// One block, warp w handles batch w.
// ---------------------------------------------------------------------------
__global__ __launch_bounds__(256) void gate_kernel(
    const float* __restrict__ w_gate, const float* __restrict__ b_gate)
{
    const int warp = threadIdx.x >> 5;
    const int lane = threadIdx.x & 31;
    if (warp >= BB) return;

    float s[ND] = {0.f, 0.f, 0.f, 0.f};
    for (int c = lane; c < CC; c += 32) {
        float p = g_pooled[warp * CC + c];
        #pragma unroll
        for (int i = 0; i < ND; i++) s[i] += p * w_gate[i * CC + c];
    }
    #pragma unroll
    for (int i = 0; i < ND; i++)
        #pragma unroll
        for (int off = 16; off > 0; off >>= 1)
            s[i] += __shfl_xor_sync(0xFFFFFFFFu, s[i], off);

    if (lane == 0) {
        float logits[ND];
        float m = -1e30f;
        #pragma unroll
        for (int i = 0; i < ND; i++) { logits[i] = s[i] + b_gate[i]; m = fmaxf(m, logits[i]); }
        float den = 0.f;
        #pragma unroll
        for (int i = 0; i < ND; i++) { logits[i] = __expf(logits[i] - m); den += logits[i]; }
        float inv = 1.f / den;
        #pragma unroll
        for (int i = 0; i < ND; i++) g_gate[warp * ND + i] = logits[i] * inv;
    }
}

// ---------------------------------------------------------------------------
// Dilated 3x3 attention + gate, fused epilogue.
// One thread per output pixel per head. blockIdx.y = branch*2 + head.
// Zero-padded unfold semantics: OOB patches contribute score 0 (NOT -inf)
// and value 0, exactly like the reference.
// ---------------------------------------------------------------------------
__global__ __launch_bounds__(128) void attn_kernel(float* __restrict__ out)
{
    const int n  = blockIdx.x * 128 + threadIdx.x;  // 0..4095
    const int bh = blockIdx.y;                      // 0..7
    const int b  = blockIdx.z;
    const int branch = bh >> 1;
    const int dil    = 1 << branch;                 // 1,2,4,8
    const int qc     = branch * BD + (bh & 1) * HD; // channel base within 512-block

    const float* qp = g_qkv + ((size_t)b * OC + qc) * NPIX;
    const float* kp = qp + (size_t)CC * NPIX;
    const float* vp = qp + (size_t)(2 * CC) * NPIX;

    const int y  = n >> 6;
    const int xx = n & 63;

    // Load q vector into registers
    float q[HD];
    #pragma unroll
    for (int d = 0; d < HD; d++) q[d] = qp[d * NPIX + n];

    // Scores for 9 patches
    float sc[9];
    int n2s[9];
    #pragma unroll
    for (int p = 0; p < 9; p++) {
        const int y2 = y + (p / 3 - 1) * dil;
        const int x2 = xx + (p % 3 - 1) * dil;
        const bool ok = ((unsigned)y2 < 64u) && ((unsigned)x2 < 64u);
        const int n2 = y2 * 64 + x2;
        n2s[p] = ok ? n2 : -1;
        float s = 0.f;
        if (ok) {
            #pragma unroll
            for (int d = 0; d < HD; d++)
                s = fmaf(q[d], kp[d * NPIX + n2], s);
        }
        sc[p] = s * 0.125f;  // hd^-0.5 = 64^-0.5
    }

    // Softmax over 9 (OOB entries participate with score 0, value 0)
    float m = sc[0];
    #pragma unroll
    for (int p = 1; p < 9; p++) m = fmaxf(m, sc[p]);
    float den = 0.f;
    #pragma unroll
    for (int p = 0; p < 9; p++) { sc[p] = __expf(sc[p] - m); den += sc[p]; }
    const float inv = 1.f / den;

    // Weighted sum of v patches
    float o[HD];
    #pragma unroll
    for (int d = 0; d < HD; d++) o[d] = 0.f;
    #pragma unroll
    for (int p = 0; p < 9; p++) {
        if (n2s[p] >= 0) {
            const float wgt = sc[p] * inv;
            const int n2 = n2s[p];
            #pragma unroll
            for (int d = 0; d < HD; d++)
                o[d] = fmaf(wgt, vp[d * NPIX + n2], o[d]);
        }
    }

    // Gate + store
    const float g = g_gate[b * ND + branch];
    float* op = out + ((size_t)b * CC + qc) * NPIX + n;
    #pragma unroll
    for (int d = 0; d < HD; d++) op[d * NPIX] = o[d] * g;
}

// ---------------------------------------------------------------------------
// Launch
// ---------------------------------------------------------------------------
extern "C" void kernel_launch(void* const* d_in, const int* in_sizes, int n_in,
                              void* d_out, int out_size)
{
    (void)in_sizes; (void)n_in; (void)out_size;
    const float* x      = (const float*)d_in[0];  // (8, 512, 64, 64)
    const float* w_qkv  = (const float*)d_in[1];  // (1536, 512)
    const float* w_gate = (const float*)d_in[2];  // (4, 512)
    const float* b_gate = (const float*)d_in[3];  // (4,)
    float* out = (float*)d_out;                   // (8, 512, 64, 64)

    // Gate path (independent of GEMM)
    pool_kernel<<<dim3(CC, BB), 256>>>(x);
    gate_kernel<<<1, 256>>>(w_gate, b_gate);

    // QKV projection
    gemm_qkv_kernel<<<dim3(NPIX / BN, OC / BM, BB), 256>>>(x, w_qkv);

    // Attention + gate + store
    attn_kernel<<<dim3(NPIX / 128, 2 * ND, BB), 128>>>(out);
}

// round 4
// speedup vs baseline: 1.9772x; 1.9772x over previous
#include <cuda_runtime.h>
#include <cuda_bf16.h>
#include <cstdint>

// Problem constants
#define BB   8
#define CC   512
#define NPIX 4096
#define OC   1536
#define ND   4
#define BD   128
#define HD   64

// Scratch (static device allocations — allowed)
__device__ __align__(16) float g_qkv[(size_t)BB * OC * NPIX];   // 192 MB
__device__ float g_pooled[BB * CC];
__device__ float g_gate[BB * ND];
__device__ __align__(16) __nv_bfloat16 g_whi[OC * CC];
__device__ __align__(16) __nv_bfloat16 g_wlo[OC * CC];
__device__ __align__(16) __nv_bfloat16 g_xhi[(size_t)BB * NPIX * CC];  // [b][n][c]
__device__ __align__(16) __nv_bfloat16 g_xlo[(size_t)BB * NPIX * CC];

// ---------------------------------------------------------------------------
// PTX helpers (sm_80+ features only — no 'a'-suffix instructions)
// ---------------------------------------------------------------------------
__device__ __forceinline__ uint32_t smem_u32(const void* p) {
    uint32_t a;
    asm("{ .reg .u64 t; cvta.to.shared.u64 t, %1; cvt.u32.u64 %0, t; }"
        : "=r"(a) : "l"(p));
    return a;
}
__device__ __forceinline__ void cp_async16(uint32_t s, const void* g) {
    asm volatile("cp.async.cg.shared.global [%0], [%1], 16;" :: "r"(s), "l"(g));
}
__device__ __forceinline__ void cp_commit() {
    asm volatile("cp.async.commit_group;" ::: "memory");
}
template <int N>
__device__ __forceinline__ void cp_wait() {
    asm volatile("cp.async.wait_group %0;" :: "n"(N) : "memory");
}
__device__ __forceinline__ void ldsm_x4(uint32_t& r0, uint32_t& r1,
                                        uint32_t& r2, uint32_t& r3, uint32_t a) {
    asm volatile("ldmatrix.sync.aligned.m8n8.x4.shared.b16 {%0,%1,%2,%3}, [%4];"
                 : "=r"(r0), "=r"(r1), "=r"(r2), "=r"(r3) : "r"(a));
}
__device__ __forceinline__ void mma_bf16(float* d, const uint32_t* a, const uint32_t* b) {
    asm volatile("mma.sync.aligned.m16n8k16.row.col.f32.bf16.bf16.f32 "
                 "{%0,%1,%2,%3}, {%4,%5,%6,%7}, {%8,%9}, {%0,%1,%2,%3};"
                 : "+f"(d[0]), "+f"(d[1]), "+f"(d[2]), "+f"(d[3])
                 : "r"(a[0]), "r"(a[1]), "r"(a[2]), "r"(a[3]),
                   "r"(b[0]), "r"(b[1]));
}

// ---------------------------------------------------------------------------
// Pre-pass 1: split w into bf16 hi/lo
// ---------------------------------------------------------------------------
__global__ __launch_bounds__(256) void split_w_kernel(const float* __restrict__ w)
{
    int i = blockIdx.x * 256 + threadIdx.x;
    float v = w[i];
    __nv_bfloat16 hi = __float2bfloat16(v);
    g_whi[i] = hi;
    g_wlo[i] = __float2bfloat16(v - __bfloat162float(hi));
}

// ---------------------------------------------------------------------------
// Pre-pass 2: transpose x [b][c][n] -> [b][n][c] + split into bf16 hi/lo
// ---------------------------------------------------------------------------
__global__ __launch_bounds__(256) void tsx_kernel(const float* __restrict__ x)
{
    __shared__ float t[32][33];
    const int b  = blockIdx.z;
    const int n0 = blockIdx.x * 32;
    const int c0 = blockIdx.y * 32;
    const int tx = threadIdx.x, ty = threadIdx.y;

    #pragma unroll
    for (int i = ty; i < 32; i += 8)
        t[i][tx] = x[((size_t)b * CC + c0 + i) * NPIX + n0 + tx];
    __syncthreads();
    #pragma unroll
    for (int i = ty; i < 32; i += 8) {
        float v = t[tx][i];
        __nv_bfloat16 hi = __float2bfloat16(v);
        size_t o = ((size_t)b * NPIX + n0 + i) * CC + c0 + tx;
        g_xhi[o] = hi;
        g_xlo[o] = __float2bfloat16(v - __bfloat162float(hi));
    }
}

// ---------------------------------------------------------------------------
// bf16 3-split GEMM via mma.sync: g_qkv[b][o][n] = sum_c w[o][c] x[b][c][n]
// 128x128 CTA tile, 8 warps (4m x 2n), warp tile 32x64, K chunk 32,
// cp.async double-buffered SMEM.
// ---------------------------------------------------------------------------
#define KC        32
#define ROWB      80              // padded row stride in bytes (32 bf16 = 64B + 16B pad)
#define TILE_SZ   (128 * ROWB)    // 10240B
#define T_AHI     0
#define T_ALO     (1 * TILE_SZ)
#define T_BHI     (2 * TILE_SZ)
#define T_BLO     (3 * TILE_SZ)
#define BUF_SZ    (4 * TILE_SZ)   // 40960B
#define GEMM_SMEM (2 * BUF_SZ)    // 81920B

__global__ __launch_bounds__(256) void gemm_mma_kernel()
{
    extern __shared__ char smem[];
    const uint32_t sb = smem_u32(smem);
    const int tid = threadIdx.x;
    const int wid = tid >> 5;
    const int lane = tid & 31;
    const int warp_m = wid >> 1;          // 0..3
    const int warp_n = wid & 1;           // 0..1
    const int b     = blockIdx.z;
    const int mBase = blockIdx.x * 128;   // m fastest for B-tile L2 reuse
    const int nBase = blockIdx.y * 128;

    const __nv_bfloat16* whiB = g_whi + (size_t)mBase * CC;
    const __nv_bfloat16* wloB = g_wlo + (size_t)mBase * CC;
    const __nv_bfloat16* xhiB = g_xhi + ((size_t)b * NPIX + nBase) * CC;
    const __nv_bfloat16* xloB = g_xlo + ((size_t)b * NPIX + nBase) * CC;

    // Loader mapping: 512 16B-units per tile; each thread does 2 per tile.
    const int u0  = tid * 2;
    const int row0 = u0 >> 2;             // 0..127
    const int seg0 = u0 & 3;              // 0 or 2 (two consecutive segs, same row)
    const uint32_t sm_off0 = (uint32_t)(row0 * ROWB + seg0 * 16);
    const size_t   gm_off0 = (size_t)row0 * CC + seg0 * 8;

    auto stage = [&](int c) {
        const uint32_t bufS = sb + (uint32_t)((c & 1) * BUF_SZ);
        const int kc = c * KC;
        #pragma unroll
        for (int i = 0; i < 2; i++) {
            const uint32_t so = sm_off0 + i * 16;
            const size_t   go = gm_off0 + i * 8 + kc;
            cp_async16(bufS + T_AHI + so, whiB + go);
            cp_async16(bufS + T_ALO + so, wloB + go);
            cp_async16(bufS + T_BHI + so, xhiB + go);
            cp_async16(bufS + T_BLO + so, xloB + go);
        }
        cp_commit();
    };

    float acc[2][8][4];
    #pragma unroll
    for (int mt = 0; mt < 2; mt++)
        #pragma unroll
        for (int nt = 0; nt < 8; nt++)
            #pragma unroll
            for (int r = 0; r < 4; r++) acc[mt][nt][r] = 0.f;

    stage(0);

    const int NCH = CC / KC;   // 16
    for (int c = 0; c < NCH; c++) {
        if (c + 1 < NCH) { stage(c + 1); cp_wait<1>(); }
        else             { cp_wait<0>(); }
        __syncthreads();

        const uint32_t bufS = sb + (uint32_t)((c & 1) * BUF_SZ);
        // ldmatrix address components
        const uint32_t aRow = (uint32_t)(warp_m * 32 + (lane & 15));
        const uint32_t aByt = (uint32_t)((lane >> 4) * 16);
        const uint32_t bRow = (uint32_t)(warp_n * 64 + ((lane >> 4) << 3) + (lane & 7));
        const uint32_t bByt = (uint32_t)(((lane >> 3) & 1) * 16);

        #pragma unroll
        for (int ks = 0; ks < 2; ks++) {
            const uint32_t kOff = (uint32_t)(ks * 32);
            uint32_t ahi[2][4], alo[2][4];
            #pragma unroll
            for (int mt = 0; mt < 2; mt++) {
                const uint32_t ao = (aRow + mt * 16) * ROWB + kOff + aByt;
                ldsm_x4(ahi[mt][0], ahi[mt][1], ahi[mt][2], ahi[mt][3],
                        bufS + T_AHI + ao);
                ldsm_x4(alo[mt][0], alo[mt][1], alo[mt][2], alo[mt][3],
                        bufS + T_ALO + ao);
            }
            #pragma unroll
            for (int np = 0; np < 4; np++) {      // pairs of n8 tiles
                const uint32_t bo = (bRow + np * 16) * ROWB + kOff + bByt;
                uint32_t bhi[4], blo[4];
                ldsm_x4(bhi[0], bhi[1], bhi[2], bhi[3], bufS + T_BHI + bo);
                ldsm_x4(blo[0], blo[1], blo[2], blo[3], bufS + T_BLO + bo);
                #pragma unroll
                for (int mt = 0; mt < 2; mt++) {
                    #pragma unroll
                    for (int j = 0; j < 2; j++) {
                        float* d = acc[mt][np * 2 + j];
                        mma_bf16(d, ahi[mt], bhi + 2 * j);
                        mma_bf16(d, ahi[mt], blo + 2 * j);
                        mma_bf16(d, alo[mt], bhi + 2 * j);
                    }
                }
            }
        }
        __syncthreads();
    }

    // Epilogue: direct fp32 stores (coalesced in 32B sectors)
    const int rBase = mBase + warp_m * 32 + (lane >> 2);
    const int cBase = nBase + warp_n * 64 + (lane & 3) * 2;
    #pragma unroll
    for (int mt = 0; mt < 2; mt++) {
        #pragma unroll
        for (int nt = 0; nt < 8; nt++) {
            const int rr = rBase + mt * 16;
            const int cc = cBase + nt * 8;
            float* p0 = g_qkv + ((size_t)b * OC + rr) * NPIX + cc;
            float* p1 = g_qkv + ((size_t)b * OC + rr + 8) * NPIX + cc;
            *reinterpret_cast<float2*>(p0) = make_float2(acc[mt][nt][0], acc[mt][nt][1]);
            *reinterpret_cast<float2*>(p1) = make_float2(acc[mt][nt][2], acc[mt][nt][3]);
        }
    }
}

// ---------------------------------------------------------------------------
// Spatial mean pool
// ---------------------------------------------------------------------------
__global__ __launch_bounds__(256) void pool_kernel(const float* __restrict__ x)
{
    const int c = blockIdx.x;
    const int b = blockIdx.y;
    const float* p = x + ((size_t)b * CC + c) * NPIX;

    float s = 0.f;
    for (int i = threadIdx.x; i < NPIX; i += 256) s += p[i];
    #pragma unroll
    for (int off = 16; off > 0; off >>= 1)
        s += __shfl_xor_sync(0xFFFFFFFFu, s, off);
    __shared__ float sred[8];
    if ((threadIdx.x & 31) == 0) sred[threadIdx.x >> 5] = s;
    __syncthreads();
    if (threadIdx.x == 0) {
        float tot = 0.f;
        #pragma unroll
        for (int i = 0; i < 8; i++) tot += sred[i];
        g_pooled[b * CC + c] = tot * (1.0f / NPIX);
    }
}

// ---------------------------------------------------------------------------
// Gate
// ---------------------------------------------------------------------------
__global__ __launch_bounds__(256) void gate_kernel(
    const float* __restrict__ w_gate, const float* __restrict__ b_gate)
{
    const int warp = threadIdx.x >> 5;
    const int lane = threadIdx.x & 31;
    if (warp >= BB) return;

    float s[ND] = {0.f, 0.f, 0.f, 0.f};
    for (int c = lane; c < CC; c += 32) {
        float p = g_pooled[warp * CC + c];
        #pragma unroll
        for (int i = 0; i < ND; i++) s[i] += p * w_gate[i * CC + c];
    }
    #pragma unroll
    for (int i = 0; i < ND; i++)
        #pragma unroll
        for (int off = 16; off > 0; off >>= 1)
            s[i] += __shfl_xor_sync(0xFFFFFFFFu, s[i], off);

    if (lane == 0) {
        float logits[ND];
        float m = -1e30f;
        #pragma unroll
        for (int i = 0; i < ND; i++) { logits[i] = s[i] + b_gate[i]; m = fmaxf(m, logits[i]); }
        float den = 0.f;
        #pragma unroll
        for (int i = 0; i < ND; i++) { logits[i] = __expf(logits[i] - m); den += logits[i]; }
        float inv = 1.f / den;
        #pragma unroll
        for (int i = 0; i < ND; i++) g_gate[warp * ND + i] = logits[i] * inv;
    }
}

// ---------------------------------------------------------------------------
// Dilated 3x3 attention + gate (two 32-d halves to cut register pressure)
// ---------------------------------------------------------------------------
__global__ __launch_bounds__(128) void attn_kernel(float* __restrict__ out)
{
    const int n  = blockIdx.x * 128 + threadIdx.x;
    const int bh = blockIdx.y;
    const int b  = blockIdx.z;
    const int branch = bh >> 1;
    const int dil    = 1 << branch;
    const int qc     = branch * BD + (bh & 1) * HD;

    const float* qp = g_qkv + ((size_t)b * OC + qc) * NPIX;
    const float* kp = qp + (size_t)CC * NPIX;
    const float* vp = qp + (size_t)(2 * CC) * NPIX;

    const int y  = n >> 6;
    const int xx = n & 63;

    int n2s[9];
    float sc[9];
    #pragma unroll
    for (int p = 0; p < 9; p++) {
        const int y2 = y + (p / 3 - 1) * dil;
        const int x2 = xx + (p % 3 - 1) * dil;
        const bool ok = ((unsigned)y2 < 64u) && ((unsigned)x2 < 64u);
        n2s[p] = ok ? y2 * 64 + x2 : -1;
        sc[p] = 0.f;
    }

    #pragma unroll
    for (int dh = 0; dh < 2; dh++) {
        float q[32];
        #pragma unroll
        for (int d = 0; d < 32; d++) q[d] = qp[(dh * 32 + d) * NPIX + n];
        #pragma unroll
        for (int p = 0; p < 9; p++) {
            if (n2s[p] >= 0) {
                float s = 0.f;
                #pragma unroll
                for (int d = 0; d < 32; d++)
                    s = fmaf(q[d], kp[(dh * 32 + d) * NPIX + n2s[p]], s);
                sc[p] += s;
            }
        }
    }
    #pragma unroll
    for (int p = 0; p < 9; p++) sc[p] *= 0.125f;

    float m = sc[0];
    #pragma unroll
    for (int p = 1; p < 9; p++) m = fmaxf(m, sc[p]);
    float den = 0.f;
    #pragma unroll
    for (int p = 0; p < 9; p++) { sc[p] = __expf(sc[p] - m); den += sc[p]; }
    const float inv = 1.f / den;
    #pragma unroll
    for (int p = 0; p < 9; p++) sc[p] *= inv;

    const float g = g_gate[b * ND + branch];
    float* op = out + ((size_t)b * CC + qc) * NPIX + n;

    #pragma unroll
    for (int dh = 0; dh < 2; dh++) {
        float o[32];
        #pragma unroll
        for (int d = 0; d < 32; d++) o[d] = 0.f;
        #pragma unroll
        for (int p = 0; p < 9; p++) {
            if (n2s[p] >= 0) {
                const float wgt = sc[p];
                const int n2 = n2s[p];
                #pragma unroll
                for (int d = 0; d < 32; d++)
                    o[d] = fmaf(wgt, vp[(dh * 32 + d) * NPIX + n2], o[d]);
            }
        }
        #pragma unroll
        for (int d = 0; d < 32; d++)
            op[(dh * 32 + d) * NPIX] = o[d] * g;
    }
}

// ---------------------------------------------------------------------------
// Launch
// ---------------------------------------------------------------------------
extern "C" void kernel_launch(void* const* d_in, const int* in_sizes, int n_in,
                              void* d_out, int out_size)
{
    (void)in_sizes; (void)n_in; (void)out_size;
    const float* x      = (const float*)d_in[0];  // (8, 512, 64, 64)
    const float* w_qkv  = (const float*)d_in[1];  // (1536, 512)
    const float* w_gate = (const float*)d_in[2];  // (4, 512)
    const float* b_gate = (const float*)d_in[3];  // (4,)
    float* out = (float*)d_out;                   // (8, 512, 64, 64)

    // Unconditional (no static guards): cheap host-side attribute set,
    // enqueues nothing, safe under graph capture.
    cudaFuncSetAttribute(gemm_mma_kernel,
                         cudaFuncAttributeMaxDynamicSharedMemorySize, GEMM_SMEM);

    // Gate path (independent)
    pool_kernel<<<dim3(CC, BB), 256>>>(x);
    gate_kernel<<<1, 256>>>(w_gate, b_gate);

    // Split / transpose pre-pass
    split_w_kernel<<<(OC * CC) / 256, 256>>>(w_qkv);
    tsx_kernel<<<dim3(NPIX / 32, CC / 32, BB), dim3(32, 8)>>>(x);

    // Tensor-core QKV projection (m fastest for B-tile reuse)
    gemm_mma_kernel<<<dim3(OC / 128, NPIX / 128, BB), 256, GEMM_SMEM>>>();

    // Attention + gate + store
    attn_kernel<<<dim3(NPIX / 128, 2 * ND, BB), 128>>>(out);
}

// round 5
// speedup vs baseline: 3.5868x; 1.8140x over previous
#include <cuda_runtime.h>
#include <cuda_fp16.h>
#include <cstdint>

// Problem constants
#define BB   8
#define CC   512
#define NPIX 4096
#define OC   1536
#define ND   4
#define BD   128
#define HD   64

// Scratch (static device allocations — allowed)
__device__ __align__(16) float g_qkv[(size_t)BB * OC * NPIX];   // 192 MB
__device__ float g_pooled[BB * CC];
__device__ float g_gate[BB * ND];
__device__ __align__(16) __half g_wh[OC * CC];                  // fp16 w
__device__ __align__(16) __half g_xh[(size_t)BB * NPIX * CC];   // fp16 x, [b][n][c]

// ---------------------------------------------------------------------------
// PTX helpers (sm_80+ only)
// ---------------------------------------------------------------------------
__device__ __forceinline__ uint32_t smem_u32(const void* p) {
    uint32_t a;
    asm("{ .reg .u64 t; cvta.to.shared.u64 t, %1; cvt.u32.u64 %0, t; }"
        : "=r"(a) : "l"(p));
    return a;
}
__device__ __forceinline__ void cp_async16(uint32_t s, const void* g) {
    asm volatile("cp.async.cg.shared.global [%0], [%1], 16;" :: "r"(s), "l"(g));
}
__device__ __forceinline__ void cp_commit() {
    asm volatile("cp.async.commit_group;" ::: "memory");
}
template <int N>
__device__ __forceinline__ void cp_wait() {
    asm volatile("cp.async.wait_group %0;" :: "n"(N) : "memory");
}
__device__ __forceinline__ void ldsm_x4(uint32_t& r0, uint32_t& r1,
                                        uint32_t& r2, uint32_t& r3, uint32_t a) {
    asm volatile("ldmatrix.sync.aligned.m8n8.x4.shared.b16 {%0,%1,%2,%3}, [%4];"
                 : "=r"(r0), "=r"(r1), "=r"(r2), "=r"(r3) : "r"(a));
}
__device__ __forceinline__ void mma_fp16(float* d, const uint32_t* a, const uint32_t* b) {
    asm volatile("mma.sync.aligned.m16n8k16.row.col.f32.f16.f16.f32 "
                 "{%0,%1,%2,%3}, {%4,%5,%6,%7}, {%8,%9}, {%0,%1,%2,%3};"
                 : "+f"(d[0]), "+f"(d[1]), "+f"(d[2]), "+f"(d[3])
                 : "r"(a[0]), "r"(a[1]), "r"(a[2]), "r"(a[3]),
                   "r"(b[0]), "r"(b[1]));
}

// ---------------------------------------------------------------------------
// Zero the pooled accumulator (persistent device global)
// ---------------------------------------------------------------------------
__global__ void zero_pool_kernel()
{
    int i = blockIdx.x * 256 + threadIdx.x;
    if (i < BB * CC) g_pooled[i] = 0.f;
}

// ---------------------------------------------------------------------------
// Pre-pass 1: w -> fp16
// ---------------------------------------------------------------------------
__global__ __launch_bounds__(256) void split_w_kernel(const float* __restrict__ w)
{
    int i = blockIdx.x * 256 + threadIdx.x;
    g_wh[i] = __float2half(w[i]);
}

// ---------------------------------------------------------------------------
// Pre-pass 2: transpose x [b][c][n] -> [b][n][c] as fp16, fused mean-pool
// partial sums (atomicAdd of raw sums; gate divides by NPIX).
// ---------------------------------------------------------------------------
__global__ __launch_bounds__(256) void tsx_kernel(const float* __restrict__ x)
{
    __shared__ float t[32][33];
    const int b  = blockIdx.z;
    const int n0 = blockIdx.x * 32;
    const int c0 = blockIdx.y * 32;
    const int tx = threadIdx.x, ty = threadIdx.y;

    #pragma unroll
    for (int i = ty; i < 32; i += 8)
        t[i][tx] = x[((size_t)b * CC + c0 + i) * NPIX + n0 + tx];
    __syncthreads();

    float psum = 0.f;
    #pragma unroll
    for (int i = ty; i < 32; i += 8) {
        float v = t[tx][i];   // x[c0+tx][n0+i]
        psum += v;
        g_xh[((size_t)b * NPIX + n0 + i) * CC + c0 + tx] = __float2half(v);
    }
    __syncthreads();
    t[ty][tx] = psum;          // partial sum for channel c0+tx, group ty
    __syncthreads();
    if (ty == 0) {
        float s = 0.f;
        #pragma unroll
        for (int j = 0; j < 8; j++) s += t[j][tx];
        atomicAdd(&g_pooled[b * CC + c0 + tx], s);
    }
}

// ---------------------------------------------------------------------------
// fp16 single-pass GEMM via mma.sync: g_qkv[b][o][n] = sum_c w[o][c] x[b][c][n]
// 128x128 CTA tile, 8 warps (4m x 2n), K chunk 32, 3-stage cp.async pipeline.
// ---------------------------------------------------------------------------
#define KC        32
#define ROWB      80               // 32 fp16 = 64B + 16B pad
#define TILE_SZ   (128 * ROWB)     // 10240B
#define T_A       0
#define T_B       TILE_SZ
#define STAGE_SZ  (2 * TILE_SZ)    // 20480B
#define NSTAGE    3
#define GEMM_SMEM (NSTAGE * STAGE_SZ)  // 61440B

__global__ __launch_bounds__(256, 2) void gemm_mma_kernel()
{
    extern __shared__ char smem[];
    const uint32_t sb = smem_u32(smem);
    const int tid = threadIdx.x;
    const int wid = tid >> 5;
    const int lane = tid & 31;
    const int warp_m = wid >> 1;          // 0..3
    const int warp_n = wid & 1;           // 0..1
    const int b     = blockIdx.z;
    const int mBase = blockIdx.x * 128;   // m fastest for B-tile L2 reuse
    const int nBase = blockIdx.y * 128;

    const __half* wB = g_wh + (size_t)mBase * CC;
    const __half* xB = g_xh + ((size_t)b * NPIX + nBase) * CC;

    // Loader: 512 16B-units per tile; each thread: 2 units A + 2 units B.
    const int u0   = tid * 2;
    const int row0 = u0 >> 2;             // 0..127
    const int seg0 = u0 & 3;              // 0 or 2
    const uint32_t sm_off0 = (uint32_t)(row0 * ROWB + seg0 * 16);
    const size_t   gm_off0 = (size_t)row0 * CC + seg0 * 8;

    auto stage = [&](int c) {
        const uint32_t bufS = sb + (uint32_t)((c % NSTAGE) * STAGE_SZ);
        const int kc = c * KC;
        #pragma unroll
        for (int i = 0; i < 2; i++) {
            const uint32_t so = sm_off0 + i * 16;
            const size_t   go = gm_off0 + i * 8 + kc;
            cp_async16(bufS + T_A + so, wB + go);
            cp_async16(bufS + T_B + so, xB + go);
        }
        cp_commit();
    };

    float acc[2][8][4];
    #pragma unroll
    for (int mt = 0; mt < 2; mt++)
        #pragma unroll
        for (int nt = 0; nt < 8; nt++)
            #pragma unroll
            for (int r = 0; r < 4; r++) acc[mt][nt][r] = 0.f;

    stage(0);
    stage(1);

    // ldmatrix address components
    const uint32_t aRow = (uint32_t)(warp_m * 32 + (lane & 15));
    const uint32_t aByt = (uint32_t)((lane >> 4) * 16);
    const uint32_t bRow = (uint32_t)(warp_n * 64 + ((lane >> 4) << 3) + (lane & 7));
    const uint32_t bByt = (uint32_t)(((lane >> 3) & 1) * 16);

    const int NCH = CC / KC;   // 16
    for (int c = 0; c < NCH; c++) {
        if (c + 2 < NCH) { stage(c + 2); cp_wait<2>(); }
        else if (c + 1 < NCH) { cp_wait<1>(); }
        else { cp_wait<0>(); }
        __syncthreads();

        const uint32_t bufS = sb + (uint32_t)((c % NSTAGE) * STAGE_SZ);

        #pragma unroll
        for (int ks = 0; ks < 2; ks++) {
            const uint32_t kOff = (uint32_t)(ks * 32);
            uint32_t af[2][4];
            #pragma unroll
            for (int mt = 0; mt < 2; mt++) {
                const uint32_t ao = (aRow + mt * 16) * ROWB + kOff + aByt;
                ldsm_x4(af[mt][0], af[mt][1], af[mt][2], af[mt][3],
                        bufS + T_A + ao);
            }
            #pragma unroll
            for (int np = 0; np < 4; np++) {      // pairs of n8 tiles
                const uint32_t bo = (bRow + np * 16) * ROWB + kOff + bByt;
                uint32_t bf[4];
                ldsm_x4(bf[0], bf[1], bf[2], bf[3], bufS + T_B + bo);
                #pragma unroll
                for (int mt = 0; mt < 2; mt++) {
                    #pragma unroll
                    for (int j = 0; j < 2; j++)
                        mma_fp16(acc[mt][np * 2 + j], af[mt], bf + 2 * j);
                }
            }
        }
        __syncthreads();
    }

    // Epilogue: direct fp32 stores
    const int rBase = mBase + warp_m * 32 + (lane >> 2);
    const int cBase = nBase + warp_n * 64 + (lane & 3) * 2;
    #pragma unroll
    for (int mt = 0; mt < 2; mt++) {
        #pragma unroll
        for (int nt = 0; nt < 8; nt++) {
            const int rr = rBase + mt * 16;
            const int cc = cBase + nt * 8;
            float* p0 = g_qkv + ((size_t)b * OC + rr) * NPIX + cc;
            float* p1 = g_qkv + ((size_t)b * OC + rr + 8) * NPIX + cc;
            *reinterpret_cast<float2*>(p0) = make_float2(acc[mt][nt][0], acc[mt][nt][1]);
            *reinterpret_cast<float2*>(p1) = make_float2(acc[mt][nt][2], acc[mt][nt][3]);
        }
    }
}

// ---------------------------------------------------------------------------
// Gate: softmax over ND branch logits per batch (pooled sums / NPIX)
// ---------------------------------------------------------------------------
__global__ __launch_bounds__(256) void gate_kernel(
    const float* __restrict__ w_gate, const float* __restrict__ b_gate)
{
    const int warp = threadIdx.x >> 5;
    const int lane = threadIdx.x & 31;
    if (warp >= BB) return;

    float s[ND] = {0.f, 0.f, 0.f, 0.f};
    for (int c = lane; c < CC; c += 32) {
        float p = g_pooled[warp * CC + c] * (1.0f / NPIX);
        #pragma unroll
        for (int i = 0; i < ND; i++) s[i] += p * w_gate[i * CC + c];
    }
    #pragma unroll
    for (int i = 0; i < ND; i++)
        #pragma unroll
        for (int off = 16; off > 0; off >>= 1)
            s[i] += __shfl_xor_sync(0xFFFFFFFFu, s[i], off);

    if (lane == 0) {
        float logits[ND];
        float m = -1e30f;
        #pragma unroll
        for (int i = 0; i < ND; i++) { logits[i] = s[i] + b_gate[i]; m = fmaxf(m, logits[i]); }
        float den = 0.f;
        #pragma unroll
        for (int i = 0; i < ND; i++) { logits[i] = __expf(logits[i] - m); den += logits[i]; }
        float inv = 1.f / den;
        #pragma unroll
        for (int i = 0; i < ND; i++) g_gate[warp * ND + i] = logits[i] * inv;
    }
}

// ---------------------------------------------------------------------------
// Dilated 3x3 attention + gate (two 32-d halves)
// ---------------------------------------------------------------------------
__global__ __launch_bounds__(128) void attn_kernel(float* __restrict__ out)
{
    const int n  = blockIdx.x * 128 + threadIdx.x;
    const int bh = blockIdx.y;
    const int b  = blockIdx.z;
    const int branch = bh >> 1;
    const int dil    = 1 << branch;
    const int qc     = branch * BD + (bh & 1) * HD;

    const float* qp = g_qkv + ((size_t)b * OC + qc) * NPIX;
    const float* kp = qp + (size_t)CC * NPIX;
    const float* vp = qp + (size_t)(2 * CC) * NPIX;

    const int y  = n >> 6;
    const int xx = n & 63;

    int n2s[9];
    float sc[9];
    #pragma unroll
    for (int p = 0; p < 9; p++) {
        const int y2 = y + (p / 3 - 1) * dil;
        const int x2 = xx + (p % 3 - 1) * dil;
        const bool ok = ((unsigned)y2 < 64u) && ((unsigned)x2 < 64u);
        n2s[p] = ok ? y2 * 64 + x2 : -1;
        sc[p] = 0.f;
    }

    #pragma unroll
    for (int dh = 0; dh < 2; dh++) {
        float q[32];
        #pragma unroll
        for (int d = 0; d < 32; d++) q[d] = qp[(dh * 32 + d) * NPIX + n];
        #pragma unroll
        for (int p = 0; p < 9; p++) {
            if (n2s[p] >= 0) {
                float s = 0.f;
                #pragma unroll
                for (int d = 0; d < 32; d++)
                    s = fmaf(q[d], kp[(dh * 32 + d) * NPIX + n2s[p]], s);
                sc[p] += s;
            }
        }
    }
    #pragma unroll
    for (int p = 0; p < 9; p++) sc[p] *= 0.125f;

    float m = sc[0];
    #pragma unroll
    for (int p = 1; p < 9; p++) m = fmaxf(m, sc[p]);
    float den = 0.f;
    #pragma unroll
    for (int p = 0; p < 9; p++) { sc[p] = __expf(sc[p] - m); den += sc[p]; }
    const float inv = 1.f / den;
    #pragma unroll
    for (int p = 0; p < 9; p++) sc[p] *= inv;

    const float g = g_gate[b * ND + branch];
    float* op = out + ((size_t)b * CC + qc) * NPIX + n;

    #pragma unroll
    for (int dh = 0; dh < 2; dh++) {
        float o[32];
        #pragma unroll
        for (int d = 0; d < 32; d++) o[d] = 0.f;
        #pragma unroll
        for (int p = 0; p < 9; p++) {
            if (n2s[p] >= 0) {
                const float wgt = sc[p];
                const int n2 = n2s[p];
                #pragma unroll
                for (int d = 0; d < 32; d++)
                    o[d] = fmaf(wgt, vp[(dh * 32 + d) * NPIX + n2], o[d]);
            }
        }
        #pragma unroll
        for (int d = 0; d < 32; d++)
            op[(dh * 32 + d) * NPIX] = o[d] * g;
    }
}

// ---------------------------------------------------------------------------
// Launch
// ---------------------------------------------------------------------------
extern "C" void kernel_launch(void* const* d_in, const int* in_sizes, int n_in,
                              void* d_out, int out_size)
{
    (void)in_sizes; (void)n_in; (void)out_size;
    const float* x      = (const float*)d_in[0];  // (8, 512, 64, 64)
    const float* w_qkv  = (const float*)d_in[1];  // (1536, 512)
    const float* w_gate = (const float*)d_in[2];  // (4, 512)
    const float* b_gate = (const float*)d_in[3];  // (4,)
    float* out = (float*)d_out;                   // (8, 512, 64, 64)

    cudaFuncSetAttribute(gemm_mma_kernel,
                         cudaFuncAttributeMaxDynamicSharedMemorySize, GEMM_SMEM);

    zero_pool_kernel<<<(BB * CC + 255) / 256, 256>>>();
    split_w_kernel<<<(OC * CC) / 256, 256>>>(w_qkv);

    // Transpose+convert x, fused pooled partial sums
    tsx_kernel<<<dim3(NPIX / 32, CC / 32, BB), dim3(32, 8)>>>(x);
    gate_kernel<<<1, 256>>>(w_gate, b_gate);

    // Tensor-core QKV projection (m fastest for B-tile reuse)
    gemm_mma_kernel<<<dim3(OC / 128, NPIX / 128, BB), 256, GEMM_SMEM>>>();

    // Attention + gate + store
    attn_kernel<<<dim3(NPIX / 128, 2 * ND, BB), 128>>>(out);
}

// round 6
// speedup vs baseline: 4.7801x; 1.3327x over previous
#include <cuda_runtime.h>
#include <cuda_fp16.h>
#include <cstdint>

// Problem constants
#define BB   8
#define CC   512
#define NPIX 4096
#define OC   1536
#define NQ   (OC / 4)      // quad-channel groups = 384
#define ND   4
#define BD   128
#define HD   64

// Scratch (static device allocations — allowed)
// Packed-quad fp16 qkv: layout [b][qidx][n][4], qidx = (c>>5)*8 + (c&7),
// sub = (c>>3)&3 → pixel n holds channels (c0, c0+8, c0+16, c0+24).
__device__ __align__(16) __half g_qh[(size_t)BB * OC * NPIX];   // 96 MB
__device__ float g_pooled[BB * CC];
__device__ float g_gate[BB * ND];
__device__ __align__(16) __half g_wh[OC * CC];                  // fp16 w
__device__ __align__(16) __half g_xh[(size_t)BB * NPIX * CC];   // fp16 x, [b][n][c]

// ---------------------------------------------------------------------------
// PTX helpers (sm_80+ only)
// ---------------------------------------------------------------------------
__device__ __forceinline__ uint32_t smem_u32(const void* p) {
    uint32_t a;
    asm("{ .reg .u64 t; cvta.to.shared.u64 t, %1; cvt.u32.u64 %0, t; }"
        : "=r"(a) : "l"(p));
    return a;
}
__device__ __forceinline__ void cp_async16(uint32_t s, const void* g) {
    asm volatile("cp.async.cg.shared.global [%0], [%1], 16;" :: "r"(s), "l"(g));
}
__device__ __forceinline__ void cp_commit() {
    asm volatile("cp.async.commit_group;" ::: "memory");
}
template <int N>
__device__ __forceinline__ void cp_wait() {
    asm volatile("cp.async.wait_group %0;" :: "n"(N) : "memory");
}
__device__ __forceinline__ void ldsm_x4(uint32_t& r0, uint32_t& r1,
                                        uint32_t& r2, uint32_t& r3, uint32_t a) {
    asm volatile("ldmatrix.sync.aligned.m8n8.x4.shared.b16 {%0,%1,%2,%3}, [%4];"
                 : "=r"(r0), "=r"(r1), "=r"(r2), "=r"(r3) : "r"(a));
}
__device__ __forceinline__ void mma_fp16(float* d, const uint32_t* a, const uint32_t* b) {
    asm volatile("mma.sync.aligned.m16n8k16.row.col.f32.f16.f16.f32 "
                 "{%0,%1,%2,%3}, {%4,%5,%6,%7}, {%8,%9}, {%0,%1,%2,%3};"
                 : "+f"(d[0]), "+f"(d[1]), "+f"(d[2]), "+f"(d[3])
                 : "r"(a[0]), "r"(a[1]), "r"(a[2]), "r"(a[3]),
                   "r"(b[0]), "r"(b[1]));
}
__device__ __forceinline__ uint32_t h2bits(__half2 h) {
    return *reinterpret_cast<uint32_t*>(&h);
}

// ---------------------------------------------------------------------------
// Pre-pass 1: w -> fp16, fused zeroing of the pooled accumulator
// ---------------------------------------------------------------------------
__global__ __launch_bounds__(256) void split_w_kernel(const float* __restrict__ w)
{
    int i = blockIdx.x * 256 + threadIdx.x;
    g_wh[i] = __float2half(w[i]);
    if (i < BB * CC) g_pooled[i] = 0.f;
}

// ---------------------------------------------------------------------------
// Pre-pass 2: transpose x [b][c][n] -> [b][n][c] as fp16, fused mean-pool
// partial sums (atomicAdd raw sums; gate divides by NPIX).
// ---------------------------------------------------------------------------
__global__ __launch_bounds__(256) void tsx_kernel(const float* __restrict__ x)
{
    __shared__ float t[32][33];
    const int b  = blockIdx.z;
    const int n0 = blockIdx.x * 32;
    const int c0 = blockIdx.y * 32;
    const int tx = threadIdx.x, ty = threadIdx.y;

    #pragma unroll
    for (int i = ty; i < 32; i += 8)
        t[i][tx] = x[((size_t)b * CC + c0 + i) * NPIX + n0 + tx];
    __syncthreads();

    float psum = 0.f;
    #pragma unroll
    for (int i = ty; i < 32; i += 8) {
        float v = t[tx][i];   // x[c0+tx][n0+i]
        psum += v;
        g_xh[((size_t)b * NPIX + n0 + i) * CC + c0 + tx] = __float2half(v);
    }
    __syncthreads();
    t[ty][tx] = psum;
    __syncthreads();
    if (ty == 0) {
        float s = 0.f;
        #pragma unroll
        for (int j = 0; j < 8; j++) s += t[j][tx];
        atomicAdd(&g_pooled[b * CC + c0 + tx], s);
    }
}

// ---------------------------------------------------------------------------
// fp16 GEMM via mma.sync: qkv[b][o][n] = sum_c w[o][c] x[b][c][n]
// 128x128 CTA tile, 8 warps (4m x 2n), K chunk 32, 3-stage cp.async pipeline.
// Epilogue: fp16 packed-quad stores into g_qh.
// ---------------------------------------------------------------------------
#define KC        32
#define ROWB      80               // 32 fp16 = 64B + 16B pad
#define TILE_SZ   (128 * ROWB)     // 10240B
#define T_A       0
#define T_B       TILE_SZ
#define STAGE_SZ  (2 * TILE_SZ)    // 20480B
#define NSTAGE    3
#define GEMM_SMEM (NSTAGE * STAGE_SZ)  // 61440B

__global__ __launch_bounds__(256, 2) void gemm_mma_kernel()
{
    extern __shared__ char smem[];
    const uint32_t sb = smem_u32(smem);
    const int tid = threadIdx.x;
    const int wid = tid >> 5;
    const int lane = tid & 31;
    const int warp_m = wid >> 1;          // 0..3
    const int warp_n = wid & 1;           // 0..1
    const int b     = blockIdx.z;
    const int mBase = blockIdx.x * 128;   // m fastest for B-tile L2 reuse
    const int nBase = blockIdx.y * 128;

    const __half* wB = g_wh + (size_t)mBase * CC;
    const __half* xB = g_xh + ((size_t)b * NPIX + nBase) * CC;

    // Loader: 512 16B-units per tile; each thread: 2 units A + 2 units B.
    const int u0   = tid * 2;
    const int row0 = u0 >> 2;             // 0..127
    const int seg0 = u0 & 3;              // 0 or 2
    const uint32_t sm_off0 = (uint32_t)(row0 * ROWB + seg0 * 16);
    const size_t   gm_off0 = (size_t)row0 * CC + seg0 * 8;

    auto stage = [&](int c) {
        const uint32_t bufS = sb + (uint32_t)((c % NSTAGE) * STAGE_SZ);
        const int kc = c * KC;
        #pragma unroll
        for (int i = 0; i < 2; i++) {
            const uint32_t so = sm_off0 + i * 16;
            const size_t   go = gm_off0 + i * 8 + kc;
            cp_async16(bufS + T_A + so, wB + go);
            cp_async16(bufS + T_B + so, xB + go);
        }
        cp_commit();
    };

    float acc[2][8][4];
    #pragma unroll
    for (int mt = 0; mt < 2; mt++)
        #pragma unroll
        for (int nt = 0; nt < 8; nt++)
            #pragma unroll
            for (int r = 0; r < 4; r++) acc[mt][nt][r] = 0.f;

    stage(0);
    stage(1);

    const uint32_t aRow = (uint32_t)(warp_m * 32 + (lane & 15));
    const uint32_t aByt = (uint32_t)((lane >> 4) * 16);
    const uint32_t bRow = (uint32_t)(warp_n * 64 + ((lane >> 4) << 3) + (lane & 7));
    const uint32_t bByt = (uint32_t)(((lane >> 3) & 1) * 16);

    const int NCH = CC / KC;   // 16
    for (int c = 0; c < NCH; c++) {
        if (c + 2 < NCH) { stage(c + 2); cp_wait<2>(); }
        else if (c + 1 < NCH) { cp_wait<1>(); }
        else { cp_wait<0>(); }
        __syncthreads();

        const uint32_t bufS = sb + (uint32_t)((c % NSTAGE) * STAGE_SZ);

        #pragma unroll
        for (int ks = 0; ks < 2; ks++) {
            const uint32_t kOff = (uint32_t)(ks * 32);
            uint32_t af[2][4];
            #pragma unroll
            for (int mt = 0; mt < 2; mt++) {
                const uint32_t ao = (aRow + mt * 16) * ROWB + kOff + aByt;
                ldsm_x4(af[mt][0], af[mt][1], af[mt][2], af[mt][3],
                        bufS + T_A + ao);
            }
            #pragma unroll
            for (int np = 0; np < 4; np++) {
                const uint32_t bo = (bRow + np * 16) * ROWB + kOff + bByt;
                uint32_t bf[4];
                ldsm_x4(bf[0], bf[1], bf[2], bf[3], bufS + T_B + bo);
                #pragma unroll
                for (int mt = 0; mt < 2; mt++) {
                    #pragma unroll
                    for (int j = 0; j < 2; j++)
                        mma_fp16(acc[mt][np * 2 + j], af[mt], bf + 2 * j);
                }
            }
        }
        __syncthreads();
    }

    // Epilogue: fp16 packed-quad stores.
    // Thread owns rows rr0, rr0+8 (mt=0) and rr0+16, rr0+24 (mt=1) — exactly
    // one channel-quad. One 16B store covers pixels cc, cc+1 x 4 channels.
    const int rr0  = mBase + warp_m * 32 + (lane >> 2);        // (rr0 & 31) < 8
    const int qidx = ((rr0 >> 5) << 3) | (rr0 & 7);
    __half* qb = g_qh + ((size_t)b * NQ + qidx) * ((size_t)NPIX * 4);
    const int cc0 = nBase + warp_n * 64 + (lane & 3) * 2;
    #pragma unroll
    for (int nt = 0; nt < 8; nt++) {
        const int cc = cc0 + nt * 8;
        __half2 h0 = __float22half2_rn(make_float2(acc[0][nt][0], acc[0][nt][2]));
        __half2 h1 = __float22half2_rn(make_float2(acc[1][nt][0], acc[1][nt][2]));
        __half2 h2 = __float22half2_rn(make_float2(acc[0][nt][1], acc[0][nt][3]));
        __half2 h3 = __float22half2_rn(make_float2(acc[1][nt][1], acc[1][nt][3]));
        uint4 u = make_uint4(h2bits(h0), h2bits(h1), h2bits(h2), h2bits(h3));
        *reinterpret_cast<uint4*>(qb + (size_t)cc * 4) = u;
    }
}

// ---------------------------------------------------------------------------
// Gate: one block per batch (parallelized; was grid=1 latency-bound)
// ---------------------------------------------------------------------------
__global__ __launch_bounds__(256) void gate_kernel(
    const float* __restrict__ w_gate, const float* __restrict__ b_gate)
{
    const int b = blockIdx.x;
    const int tid = threadIdx.x;
    const int lane = tid & 31;
    const int warp = tid >> 5;

    float s[ND] = {0.f, 0.f, 0.f, 0.f};
    for (int c = tid; c < CC; c += 256) {
        float p = g_pooled[b * CC + c] * (1.0f / NPIX);
        #pragma unroll
        for (int i = 0; i < ND; i++) s[i] += p * w_gate[i * CC + c];
    }
    #pragma unroll
    for (int i = 0; i < ND; i++)
        #pragma unroll
        for (int off = 16; off > 0; off >>= 1)
            s[i] += __shfl_xor_sync(0xFFFFFFFFu, s[i], off);

    __shared__ float sred[8][ND];
    if (lane == 0)
        #pragma unroll
        for (int i = 0; i < ND; i++) sred[warp][i] = s[i];
    __syncthreads();
    if (tid == 0) {
        float logits[ND];
        float m = -1e30f;
        #pragma unroll
        for (int i = 0; i < ND; i++) {
            float t = b_gate[i];
            #pragma unroll
            for (int wdx = 0; wdx < 8; wdx++) t += sred[wdx][i];
            logits[i] = t;
            m = fmaxf(m, t);
        }
        float den = 0.f;
        #pragma unroll
        for (int i = 0; i < ND; i++) { logits[i] = __expf(logits[i] - m); den += logits[i]; }
        float inv = 1.f / den;
        #pragma unroll
        for (int i = 0; i < ND; i++) g_gate[b * ND + i] = logits[i] * inv;
    }
}

// ---------------------------------------------------------------------------
// Dilated 3x3 attention + gate, fp16 packed-quad loads (uint2 = 4 channels)
// ---------------------------------------------------------------------------
__global__ __launch_bounds__(128) void attn_kernel(float* __restrict__ out)
{
    const int n  = blockIdx.x * 128 + threadIdx.x;
    const int bh = blockIdx.y;
    const int b  = blockIdx.z;
    const int branch = bh >> 1;
    const int dil    = 1 << branch;
    const int qc     = branch * BD + (bh & 1) * HD;   // multiple of 64

    // Quad-group base for this head: channels qc..qc+63 -> quads qidx0..qidx0+15
    const int qidx0 = (qc >> 5) << 3;
    const __half* qp = g_qh + ((size_t)b * NQ + qidx0) * ((size_t)NPIX * 4);
    const __half* kp = qp + (size_t)(CC / 4) * NPIX * 4;       // +512 channels
    const __half* vp = qp + (size_t)(2 * (CC / 4)) * NPIX * 4; // +1024 channels

    const int y  = n >> 6;
    const int xx = n & 63;

    int n2s[9];
    float sc[9];
    #pragma unroll
    for (int p = 0; p < 9; p++) {
        const int y2 = y + (p / 3 - 1) * dil;
        const int x2 = xx + (p % 3 - 1) * dil;
        const bool ok = ((unsigned)y2 < 64u) && ((unsigned)x2 < 64u);
        n2s[p] = ok ? y2 * 64 + x2 : -1;
        sc[p] = 0.f;
    }

    // Scores: two halves of 8 quads (32 channels) each
    #pragma unroll
    for (int th = 0; th < 2; th++) {
        float qf[32];
        #pragma unroll
        for (int t = 0; t < 8; t++) {
            uint2 u = *reinterpret_cast<const uint2*>(
                qp + ((size_t)(th * 8 + t) * NPIX + n) * 4);
            float2 a = __half22float2(*reinterpret_cast<__half2*>(&u.x));
            float2 c = __half22float2(*reinterpret_cast<__half2*>(&u.y));
            qf[t * 4 + 0] = a.x; qf[t * 4 + 1] = a.y;
            qf[t * 4 + 2] = c.x; qf[t * 4 + 3] = c.y;
        }
        #pragma unroll
        for (int p = 0; p < 9; p++) {
            if (n2s[p] >= 0) {
                float s = 0.f;
                #pragma unroll
                for (int t = 0; t < 8; t++) {
                    uint2 u = *reinterpret_cast<const uint2*>(
                        kp + ((size_t)(th * 8 + t) * NPIX + n2s[p]) * 4);
                    float2 a = __half22float2(*reinterpret_cast<__half2*>(&u.x));
                    float2 c = __half22float2(*reinterpret_cast<__half2*>(&u.y));
                    s = fmaf(qf[t * 4 + 0], a.x, s);
                    s = fmaf(qf[t * 4 + 1], a.y, s);
                    s = fmaf(qf[t * 4 + 2], c.x, s);
                    s = fmaf(qf[t * 4 + 3], c.y, s);
                }
                sc[p] += s;
            }
        }
    }
    #pragma unroll
    for (int p = 0; p < 9; p++) sc[p] *= 0.125f;

    // Softmax over 9 (OOB scores exactly 0, matching zero-pad reference)
    float m = sc[0];
    #pragma unroll
    for (int p = 1; p < 9; p++) m = fmaxf(m, sc[p]);
    float den = 0.f;
    #pragma unroll
    for (int p = 0; p < 9; p++) { sc[p] = __expf(sc[p] - m); den += sc[p]; }
    const float inv = 1.f / den;
    #pragma unroll
    for (int p = 0; p < 9; p++) sc[p] *= inv;

    const float g = g_gate[b * ND + branch];
    float* op = out + ((size_t)b * CC + qc) * NPIX + n;

    // Output: two halves; quad t (global t'=th*8+t), sub s -> d = th*32 + t + s*8
    #pragma unroll
    for (int th = 0; th < 2; th++) {
        float o[32];
        #pragma unroll
        for (int i = 0; i < 32; i++) o[i] = 0.f;
        #pragma unroll
        for (int p = 0; p < 9; p++) {
            if (n2s[p] >= 0) {
                const float wgt = sc[p];
                #pragma unroll
                for (int t = 0; t < 8; t++) {
                    uint2 u = *reinterpret_cast<const uint2*>(
                        vp + ((size_t)(th * 8 + t) * NPIX + n2s[p]) * 4);
                    float2 a = __half22float2(*reinterpret_cast<__half2*>(&u.x));
                    float2 c = __half22float2(*reinterpret_cast<__half2*>(&u.y));
                    o[t * 4 + 0] = fmaf(wgt, a.x, o[t * 4 + 0]);
                    o[t * 4 + 1] = fmaf(wgt, a.y, o[t * 4 + 1]);
                    o[t * 4 + 2] = fmaf(wgt, c.x, o[t * 4 + 2]);
                    o[t * 4 + 3] = fmaf(wgt, c.y, o[t * 4 + 3]);
                }
            }
        }
        #pragma unroll
        for (int t = 0; t < 8; t++)
            #pragma unroll
            for (int s = 0; s < 4; s++) {
                const int d = th * 32 + t + s * 8;
                op[(size_t)d * NPIX] = o[t * 4 + s] * g;
            }
    }
}

// ---------------------------------------------------------------------------
// Launch
// ---------------------------------------------------------------------------
extern "C" void kernel_launch(void* const* d_in, const int* in_sizes, int n_in,
                              void* d_out, int out_size)
{
    (void)in_sizes; (void)n_in; (void)out_size;
    const float* x      = (const float*)d_in[0];  // (8, 512, 64, 64)
    const float* w_qkv  = (const float*)d_in[1];  // (1536, 512)
    const float* w_gate = (const float*)d_in[2];  // (4, 512)
    const float* b_gate = (const float*)d_in[3];  // (4,)
    float* out = (float*)d_out;                   // (8, 512, 64, 64)

    cudaFuncSetAttribute(gemm_mma_kernel,
                         cudaFuncAttributeMaxDynamicSharedMemorySize, GEMM_SMEM);

    split_w_kernel<<<(OC * CC) / 256, 256>>>(w_qkv);          // + pooled zeroing
    tsx_kernel<<<dim3(NPIX / 32, CC / 32, BB), dim3(32, 8)>>>(x);
    gate_kernel<<<BB, 256>>>(w_gate, b_gate);

    gemm_mma_kernel<<<dim3(OC / 128, NPIX / 128, BB), 256, GEMM_SMEM>>>();

    attn_kernel<<<dim3(NPIX / 128, 2 * ND, BB), 128>>>(out);
}